// round 8
// baseline (speedup 1.0000x reference)
#include <cuda_runtime.h>
#include <cuda_bf16.h>

// Fixed shapes per reference setup_inputs
#define BB 8
#define CC 3
#define HH 224
#define WW 224
#define NPIX (HH * WW)          // 50176
#define NSEG 196
#define EE 768
#define NROWS (BB * NSEG)       // 1568
#define ACC_STRIDE 64           // 256 B per row: one LTS hash block per (rep,row)
#define NREP 4                  // accumulator replicas

#define SC_BLOCKS 392           // scatter: (BB*NPIX/4) / 256, 4 px per thread (R5 shape)
#define SC_THREADS 256
#define PR_BLOCKS 784           // project: 2 rows per block
#define PR_THREADS 384          // 192 threads per row, 4 cols (float4) each

// Scratch accumulators: 4 * 1568 * 256 B = 1.6 MB. Zero at module load; the
// project kernel re-zeroes every row it consumes, so each launch leaves the
// array zeroed for the next graph replay.
__device__ float g_acc[(long)NREP * NROWS * ACC_STRIDE];

// ---------------------------------------------------------------------------
__device__ __forceinline__ void red_add_v4(float* addr, float a, float b,
                                           float c, float d) {
    asm volatile("red.global.add.v4.f32 [%0], {%1, %2, %3, %4};"
                 :: "l"(addr), "f"(a), "f"(b), "f"(c), "f"(d) : "memory");
}
__device__ __forceinline__ void red_add_v2(float* addr, float a, float b) {
    asm volatile("red.global.add.v2.f32 [%0], {%1, %2};"
                 :: "l"(addr), "f"(a), "f"(b) : "memory");
}

// ---------------------------------------------------------------------------
// Kernel A: scatter, R5 shape (fastest measured): 4 pixels/thread, LDG.128
// input loads, 2 vector REDG per pixel into one of NREP replica accumulators.
// ---------------------------------------------------------------------------
__global__ void __launch_bounds__(SC_THREADS, 8)
scatter_kernel(const float* __restrict__ img,
               const int* __restrict__ seg) {
    int t  = blockIdx.x * SC_THREADS + threadIdx.x;   // one 4-pixel group
    int b  = t / (NPIX / 4);
    int n4 = t - b * (NPIX / 4);
    int n  = n4 * 4;                                  // pixel linear index
    int h  = n / WW;
    int w  = n - h * WW;

    const float4 r4 = *reinterpret_cast<const float4*>(img + ((long)(b * CC + 0) * NPIX + n));
    const float4 g4 = *reinterpret_cast<const float4*>(img + ((long)(b * CC + 1) * NPIX + n));
    const float4 b4 = *reinterpret_cast<const float4*>(img + ((long)(b * CC + 2) * NPIX + n));
    const int4   s4 = *reinterpret_cast<const int4*>(seg + (long)b * NPIX + n);

    const float inv = 1.0f / 223.0f;
    float y = (float)h * inv;

    float rr[4] = {r4.x, r4.y, r4.z, r4.w};
    float gg[4] = {g4.x, g4.y, g4.z, g4.w};
    float bb[4] = {b4.x, b4.y, b4.z, b4.w};
    int   ss[4] = {s4.x, s4.y, s4.z, s4.w};

    float* rep = g_acc + (long)(blockIdx.x & (NREP - 1)) * ((long)NROWS * ACC_STRIDE);

#pragma unroll
    for (int i = 0; i < 4; i++) {
        float x = (float)(w + i) * inv;
        float* base = rep + (long)(b * NSEG + ss[i]) * ACC_STRIDE;
        red_add_v4(base, rr[i], gg[i], bb[i], x);
        red_add_v2(base + 4, y, 1.0f);
    }
}

// ---------------------------------------------------------------------------
// Kernel B: project, vectorized. 2 rows per block (warps 0-5 -> row0,
// warps 6-11 -> row1). Each warp redundantly loads its row's 24 acc floats
// (lanes 0-23) and shfl-reduces. Each of the 192 threads per row then
// computes 4 consecutive output columns with float4 loads/stores:
// 7 LDG.128 + 1 STG.128 per thread (vs 24 scalar LDG before).
// ---------------------------------------------------------------------------
__global__ void __launch_bounds__(PR_THREADS, 4)
project_kernel(const float* __restrict__ Wm,
               const float* __restrict__ bias,
               float* __restrict__ out) {
    const int tid  = threadIdx.x;
    const int half = tid / 192;                // 0 or 1
    const int t    = tid - half * 192;         // thread-in-row: 0..191
    const int lane = tid & 31;
    const int s    = blockIdx.x * 2 + half;    // row 0..1567

    // lanes 0-23 of every warp load this row's acc values: rep = lane/6, j = lane%6
    float v = 0.0f;
    if (lane < NREP * 6) {
        int rep = lane / 6;
        int j   = lane - rep * 6;
        v = g_acc[(long)rep * ((long)NROWS * ACC_STRIDE)
                  + (long)s * ACC_STRIDE + j];
    }

    float a0 = __shfl_sync(0xffffffffu, v, 0)  + __shfl_sync(0xffffffffu, v, 6)
             + __shfl_sync(0xffffffffu, v, 12) + __shfl_sync(0xffffffffu, v, 18);
    float a1 = __shfl_sync(0xffffffffu, v, 1)  + __shfl_sync(0xffffffffu, v, 7)
             + __shfl_sync(0xffffffffu, v, 13) + __shfl_sync(0xffffffffu, v, 19);
    float a2 = __shfl_sync(0xffffffffu, v, 2)  + __shfl_sync(0xffffffffu, v, 8)
             + __shfl_sync(0xffffffffu, v, 14) + __shfl_sync(0xffffffffu, v, 20);
    float a3 = __shfl_sync(0xffffffffu, v, 3)  + __shfl_sync(0xffffffffu, v, 9)
             + __shfl_sync(0xffffffffu, v, 15) + __shfl_sync(0xffffffffu, v, 21);
    float a4 = __shfl_sync(0xffffffffu, v, 4)  + __shfl_sync(0xffffffffu, v, 10)
             + __shfl_sync(0xffffffffu, v, 16) + __shfl_sync(0xffffffffu, v, 22);
    float cnt = __shfl_sync(0xffffffffu, v, 5)  + __shfl_sync(0xffffffffu, v, 11)
              + __shfl_sync(0xffffffffu, v, 17) + __shfl_sync(0xffffffffu, v, 23);

    bool  empty = !(cnt > 0.0f);
    float invc = empty ? 0.0f : (1.0f / cnt);
    float m0 = a0 * invc;
    float m1 = a1 * invc;
    float m2 = a2 * invc;
    float m3 = a3 * invc;
    float m4 = a4 * invc;

    // 4 consecutive columns per thread, all float4 traffic.
    const int e = t * 4;                        // 0..764
    float4 w0 = *reinterpret_cast<const float4*>(Wm + e);
    float4 w1 = *reinterpret_cast<const float4*>(Wm + EE + e);
    float4 w2 = *reinterpret_cast<const float4*>(Wm + 2 * EE + e);
    float4 w3 = *reinterpret_cast<const float4*>(Wm + 3 * EE + e);
    float4 w4 = *reinterpret_cast<const float4*>(Wm + 4 * EE + e);
    float4 bb = *reinterpret_cast<const float4*>(bias + e);

    float4 r;
    r.x = m0 * w0.x + m1 * w1.x + m2 * w2.x + m3 * w3.x + m4 * w4.x + bb.x;
    r.y = m0 * w0.y + m1 * w1.y + m2 * w2.y + m3 * w3.y + m4 * w4.y + bb.y;
    r.z = m0 * w0.z + m1 * w1.z + m2 * w2.z + m3 * w3.z + m4 * w4.z + bb.z;
    r.w = m0 * w0.w + m1 * w1.w + m2 * w2.w + m3 * w3.w + m4 * w4.w + bb.w;
    if (empty) r = make_float4(0.f, 0.f, 0.f, 0.f);

    *reinterpret_cast<float4*>(out + (long)s * EE + e) = r;

    // Reset the consumed acc words for the next replay, after ALL warps in
    // the block finished reading their rows.
    __syncthreads();
    if (tid < 16) {                            // 2 rows * NREP * 2 float4
        int rrow = blockIdx.x * 2 + (tid >> 3);
        int rep  = (tid >> 1) & 3;
        int h4   = tid & 1;
        reinterpret_cast<float4*>(g_acc + (long)rep * ((long)NROWS * ACC_STRIDE)
                                        + (long)rrow * ACC_STRIDE)[h4] =
            make_float4(0.f, 0.f, 0.f, 0.f);
    }
}

// ---------------------------------------------------------------------------
extern "C" void kernel_launch(void* const* d_in, const int* in_sizes, int n_in,
                              void* d_out, int out_size) {
    const float* img  = (const float*)d_in[0];   // [8,3,224,224]
    const int*   seg  = (const int*)d_in[1];     // [8,224,224]
    const float* Wm   = (const float*)d_in[2];   // [5,768]
    const float* bias = (const float*)d_in[3];   // [768]
    float* out = (float*)d_out;                  // [8,196,768]

    (void)in_sizes; (void)n_in; (void)out_size;

    scatter_kernel<<<SC_BLOCKS, SC_THREADS>>>(img, seg);
    project_kernel<<<PR_BLOCKS, PR_THREADS>>>(Wm, bias, out);
}